// round 9
// baseline (speedup 1.0000x reference)
#include <cuda_runtime.h>

// z_hat [B,T,D] f32, P [B,T] f32, lengths [B] i32 -> out [B,T,D] f32
#define BB 4
#define TT 4096
#define DD 512
#define CC 256              // chunks along T
#define LL 16               // chunk length
#define D4 128              // float4 lanes per row (DD/4)
#define NCHUNK (BB*CC)      // 1024 chunks, flattened f = b*CC + c
#define NPAIR 512           // k1/k3 blocks; block j owns chunks j and 1023-j

// Scratch (__device__ globals; allocation-free rule). idx f = b*CC + c.
__device__ float g_Bsum[NCHUNK * DD];
__device__ float g_A[NCHUNK];
__device__ float g_Zinit[NCHUNK * DD];

// ---------------------------------------------------------------------------
// K1: per-chunk weighted reduction + masked zero-fill.
// 256 threads = 2 halves; half h owns chunk f = j (h=0) / 1023-j (h=1).
// Weights live in smem (keeps regs <= 64 -> 4 blocks/SM). Halves whose chunk
// is fully masked spend their time zero-filling that chunk's OUTPUT rows
// (moving that traffic off k3's critical path); k3 then skips masked chunks.
// ---------------------------------------------------------------------------
__global__ void __launch_bounds__(256, 4) k1_chunk_summary(
    const float* __restrict__ z, const float* __restrict__ P,
    const int* __restrict__ lengths, float* __restrict__ out)
{
    const int j = blockIdx.x;
    const int tid = threadIdx.x;
    const int lane = tid & 127;      // float4 lane over D
    const int h = tid >> 7;          // which chunk of the pair

    const int f = h ? (NCHUNK - 1 - j) : j;
    const int b = f >> 8;            // f / CC
    const int c = f & (CC - 1);
    const int len = lengths[b];
    const int t0 = c * LL;
    const bool active = (t0 < len);

    __shared__ float sw[2][LL];      // clamped p, then suffix weights in place
    __shared__ float sA[2];

    if (active && lane < LL) {
        float p = P[b * TT + t0 + lane];
        sw[h][lane] = fminf(fmaxf(p, 0.0f), 1.0f - 1e-6f);
    }
    __syncthreads();
    if (active && lane == 0) {
        float r = 1.0f;
#pragma unroll
        for (int k = LL - 1; k >= 0; --k) {
            float p = sw[h][k];
            sw[h][k] = fmaxf(p, 1e-6f) * r;   // w[k] = pe[k]*prod_{m>k} q[m]
            r *= (1.0f - p);
        }
        sA[h] = r;                             // A = prod q
    }
    __syncthreads();

    if (!active) {
        // masked chunk: its output is all zeros -> fill here, k3 skips it
        float4* __restrict__ op = (float4*)(out + ((size_t)b * TT + t0) * DD);
        float4 zero = make_float4(0.f, 0.f, 0.f, 0.f);
#pragma unroll
        for (int k = 0; k < LL; ++k) op[(size_t)k * D4 + lane] = zero;
        return;                                // after both syncs -> safe
    }

    const float4* __restrict__ zp =
        (const float4*)(z + ((size_t)b * TT + t0) * DD);

    float4 a0 = make_float4(0.f, 0.f, 0.f, 0.f);
    float4 a1 = make_float4(0.f, 0.f, 0.f, 0.f);
#pragma unroll
    for (int kb = 0; kb < LL; kb += 8) {
        float4 x0 = zp[(size_t)(kb + 0) * D4 + lane];
        float4 x1 = zp[(size_t)(kb + 1) * D4 + lane];
        float4 x2 = zp[(size_t)(kb + 2) * D4 + lane];
        float4 x3 = zp[(size_t)(kb + 3) * D4 + lane];
        float4 x4 = zp[(size_t)(kb + 4) * D4 + lane];
        float4 x5 = zp[(size_t)(kb + 5) * D4 + lane];
        float4 x6 = zp[(size_t)(kb + 6) * D4 + lane];
        float4 x7 = zp[(size_t)(kb + 7) * D4 + lane];
        asm volatile("" ::: "memory");       // keep the 8 loads front-batched
        float w0 = sw[h][kb+0], w1 = sw[h][kb+1], w2 = sw[h][kb+2], w3 = sw[h][kb+3];
        float w4 = sw[h][kb+4], w5 = sw[h][kb+5], w6 = sw[h][kb+6], w7 = sw[h][kb+7];
        a0.x = fmaf(w0, x0.x, a0.x); a0.y = fmaf(w0, x0.y, a0.y);
        a0.z = fmaf(w0, x0.z, a0.z); a0.w = fmaf(w0, x0.w, a0.w);
        a1.x = fmaf(w1, x1.x, a1.x); a1.y = fmaf(w1, x1.y, a1.y);
        a1.z = fmaf(w1, x1.z, a1.z); a1.w = fmaf(w1, x1.w, a1.w);
        a0.x = fmaf(w2, x2.x, a0.x); a0.y = fmaf(w2, x2.y, a0.y);
        a0.z = fmaf(w2, x2.z, a0.z); a0.w = fmaf(w2, x2.w, a0.w);
        a1.x = fmaf(w3, x3.x, a1.x); a1.y = fmaf(w3, x3.y, a1.y);
        a1.z = fmaf(w3, x3.z, a1.z); a1.w = fmaf(w3, x3.w, a1.w);
        a0.x = fmaf(w4, x4.x, a0.x); a0.y = fmaf(w4, x4.y, a0.y);
        a0.z = fmaf(w4, x4.z, a0.z); a0.w = fmaf(w4, x4.w, a0.w);
        a1.x = fmaf(w5, x5.x, a1.x); a1.y = fmaf(w5, x5.y, a1.y);
        a1.z = fmaf(w5, x5.z, a1.z); a1.w = fmaf(w5, x5.w, a1.w);
        a0.x = fmaf(w6, x6.x, a0.x); a0.y = fmaf(w6, x6.y, a0.y);
        a0.z = fmaf(w6, x6.z, a0.z); a0.w = fmaf(w6, x6.w, a0.w);
        a1.x = fmaf(w7, x7.x, a1.x); a1.y = fmaf(w7, x7.y, a1.y);
        a1.z = fmaf(w7, x7.z, a1.z); a1.w = fmaf(w7, x7.w, a1.w);
    }
    float4 acc = make_float4(a0.x + a1.x, a0.y + a1.y, a0.z + a1.z, a0.w + a1.w);
    ((float4*)g_Bsum)[(size_t)f * D4 + lane] = acc;
    if (lane == 0) g_A[f] = sA[h];
}

// ---------------------------------------------------------------------------
// K2: parallel cross-chunk scan (Hillis-Steele over affine maps).
// Block = (b, d4-lane), thread c owns chunk c's map (A, Bsum[.,g]).
// Garbage in masked chunks only flows toward higher c -> never consumed.
// ---------------------------------------------------------------------------
__global__ void __launch_bounds__(CC) k2_scan()
{
    const int b = blockIdx.x;
    const int g = blockIdx.y;     // d4 lane 0..127
    const int c = threadIdx.x;    // chunk id 0..CC-1

    __shared__ float sA[CC];
    __shared__ float4 sB[CC];

    float a = g_A[b * CC + c];
    float4 v = ((const float4*)g_Bsum)[(size_t)(b * CC + c) * D4 + g];
    sA[c] = a; sB[c] = v;
    __syncthreads();

#pragma unroll
    for (int s = 1; s < CC; s <<= 1) {
        float pa = 1.0f;
        float4 pb = make_float4(0.f, 0.f, 0.f, 0.f);
        if (c >= s) { pa = sA[c - s]; pb = sB[c - s]; }
        __syncthreads();
        if (c >= s) {
            v.x = fmaf(a, pb.x, v.x);
            v.y = fmaf(a, pb.y, v.y);
            v.z = fmaf(a, pb.z, v.z);
            v.w = fmaf(a, pb.w, v.w);
            a *= pa;
            sA[c] = a; sB[c] = v;
        }
        __syncthreads();
    }

    float4 zo = (c == 0) ? make_float4(0.f, 0.f, 0.f, 0.f) : sB[c - 1];
    ((float4*)g_Zinit)[(size_t)(b * CC + c) * D4 + g] = zo;
}

// ---------------------------------------------------------------------------
// K3: per-chunk local scan seeded with Zinit; write live output only
// (masked chunks were zero-filled by K1 -> immediate exit, no stores).
// z reads are L2-warm from K1. 4-deep staging keeps regs <= 64.
// No __syncthreads -> early return is safe.
// ---------------------------------------------------------------------------
__global__ void __launch_bounds__(256, 4) k3_scan_out(
    const float* __restrict__ z, const float* __restrict__ P,
    const int* __restrict__ lengths, float* __restrict__ out)
{
    const int j = blockIdx.x;
    const int tid = threadIdx.x;
    const int lane = tid & 127;
    const int h = tid >> 7;

    const int f = h ? (NCHUNK - 1 - j) : j;
    const int b = f >> 8;
    const int c = f & (CC - 1);
    const int len = lengths[b];
    const int t0 = c * LL;
    if (t0 >= len) return;           // zero-filled by K1

    // carry load issued early (L2 latency hidden behind P loads)
    float4 zv = ((const float4*)g_Zinit)[(size_t)f * D4 + lane];

    float pc[LL];
#pragma unroll
    for (int k = 0; k < LL; ++k) {
        float p = __ldg(&P[b * TT + t0 + k]);
        pc[k] = fminf(fmaxf(p, 0.0f), 1.0f - 1e-6f);
    }

    const float4* __restrict__ zp =
        (const float4*)(z + ((size_t)b * TT + t0) * DD);
    float4* __restrict__ op = (float4*)(out + ((size_t)b * TT + t0) * DD);

#pragma unroll
    for (int kb = 0; kb < LL; kb += 4) {
        float4 x0 = zp[(size_t)(kb + 0) * D4 + lane];
        float4 x1 = zp[(size_t)(kb + 1) * D4 + lane];
        float4 x2 = zp[(size_t)(kb + 2) * D4 + lane];
        float4 x3 = zp[(size_t)(kb + 3) * D4 + lane];
        asm volatile("" ::: "memory");   // keep the 4 loads front-batched
#pragma unroll
        for (int u = 0; u < 4; ++u) {
            const int kk = kb + u;
            float4 x = (u == 0) ? x0 : (u == 1) ? x1 : (u == 2) ? x2 : x3;
            float q = 1.0f - pc[kk];
            float pe = fmaxf(pc[kk], 1e-6f);
            zv.x = fmaf(q, zv.x, pe * x.x);
            zv.y = fmaf(q, zv.y, pe * x.y);
            zv.z = fmaf(q, zv.z, pe * x.z);
            zv.w = fmaf(q, zv.w, pe * x.w);
            float m = (t0 + kk < len) ? 1.0f : 0.0f;
            op[(size_t)kk * D4 + lane] =
                make_float4(zv.x * m, zv.y * m, zv.z * m, zv.w * m);
        }
    }
}

extern "C" void kernel_launch(void* const* d_in, const int* in_sizes, int n_in,
                              void* d_out, int out_size)
{
    const float* z = (const float*)d_in[0];
    const float* P = (const float*)d_in[1];
    const int* lengths = (const int*)d_in[2];
    float* out = (float*)d_out;

    k1_chunk_summary<<<NPAIR, 256>>>(z, P, lengths, out);
    dim3 gridS(BB, D4);
    k2_scan<<<gridS, CC>>>();
    k3_scan_out<<<NPAIR, 256>>>(z, P, lengths, out);
}

// round 10
// speedup vs baseline: 1.3986x; 1.3986x over previous
#include <cuda_runtime.h>

// z_hat [B,T,D] f32, P [B,T] f32, lengths [B] i32 -> out [B,T,D] f32
#define BB 4
#define TT 4096
#define DD 512
#define CC 512              // chunks along T
#define LL 8                // chunk length
#define D4 128              // float4 lanes per row (DD/4)
#define NCHUNK (BB*CC)      // 2048 chunks, f = b*CC + c

// Scratch (__device__ globals; allocation-free rule). idx f = b*CC + c.
__device__ float g_Bsum[NCHUNK * DD];
__device__ float g_A[NCHUNK];
__device__ float g_Zinit[NCHUNK * DD];

// ---------------------------------------------------------------------------
// K1: per-chunk weighted reduction. No smem, no syncs: each thread computes
// the LL=8 suffix weights redundantly from broadcast P loads, so z loads
// issue with minimal prologue. 2048 blocks x 128 thr -> deep read queue.
//   Bsum[f,d] = sum_k w[k]*z[t0+k,d], w[k]=pe[k]*prod_{m>k}q[m]; A[f]=prod q
// ---------------------------------------------------------------------------
__global__ void __launch_bounds__(128) k1_chunk_summary(
    const float* __restrict__ z, const float* __restrict__ P,
    const int* __restrict__ lengths)
{
    const int b = blockIdx.x;     // fastest -> masked/active mixed across SMs
    const int c = blockIdx.y;
    const int lane = threadIdx.x; // float4 lane over D
    const int len = lengths[b];
    const int t0 = c * LL;
    if (t0 >= len) return;        // masked chunk: state never consumed

    // per-thread weights (broadcast loads; independent, MLP=8)
    float pcl[LL];
#pragma unroll
    for (int k = 0; k < LL; ++k) {
        float p = __ldg(&P[b * TT + t0 + k]);
        pcl[k] = fminf(fmaxf(p, 0.0f), 1.0f - 1e-6f);
    }
    float w[LL];
    float r = 1.0f;
#pragma unroll
    for (int k = LL - 1; k >= 0; --k) {
        w[k] = fmaxf(pcl[k], 1e-6f) * r;
        r *= (1.0f - pcl[k]);
    }

    const float4* __restrict__ zp =
        (const float4*)(z + ((size_t)b * TT + t0) * DD);

    float4 x0 = zp[0 * D4 + lane];
    float4 x1 = zp[1 * D4 + lane];
    float4 x2 = zp[2 * D4 + lane];
    float4 x3 = zp[3 * D4 + lane];
    float4 x4 = zp[4 * D4 + lane];
    float4 x5 = zp[5 * D4 + lane];
    float4 x6 = zp[6 * D4 + lane];
    float4 x7 = zp[7 * D4 + lane];
    asm volatile("" ::: "memory");   // keep all 8 loads front-batched

    float4 a0, a1;
    a0.x = w[0] * x0.x; a0.y = w[0] * x0.y; a0.z = w[0] * x0.z; a0.w = w[0] * x0.w;
    a1.x = w[1] * x1.x; a1.y = w[1] * x1.y; a1.z = w[1] * x1.z; a1.w = w[1] * x1.w;
    a0.x = fmaf(w[2], x2.x, a0.x); a0.y = fmaf(w[2], x2.y, a0.y);
    a0.z = fmaf(w[2], x2.z, a0.z); a0.w = fmaf(w[2], x2.w, a0.w);
    a1.x = fmaf(w[3], x3.x, a1.x); a1.y = fmaf(w[3], x3.y, a1.y);
    a1.z = fmaf(w[3], x3.z, a1.z); a1.w = fmaf(w[3], x3.w, a1.w);
    a0.x = fmaf(w[4], x4.x, a0.x); a0.y = fmaf(w[4], x4.y, a0.y);
    a0.z = fmaf(w[4], x4.z, a0.z); a0.w = fmaf(w[4], x4.w, a0.w);
    a1.x = fmaf(w[5], x5.x, a1.x); a1.y = fmaf(w[5], x5.y, a1.y);
    a1.z = fmaf(w[5], x5.z, a1.z); a1.w = fmaf(w[5], x5.w, a1.w);
    a0.x = fmaf(w[6], x6.x, a0.x); a0.y = fmaf(w[6], x6.y, a0.y);
    a0.z = fmaf(w[6], x6.z, a0.z); a0.w = fmaf(w[6], x6.w, a0.w);
    a1.x = fmaf(w[7], x7.x, a1.x); a1.y = fmaf(w[7], x7.y, a1.y);
    a1.z = fmaf(w[7], x7.z, a1.z); a1.w = fmaf(w[7], x7.w, a1.w);

    const int f = b * CC + c;
    ((float4*)g_Bsum)[(size_t)f * D4 + lane] =
        make_float4(a0.x + a1.x, a0.y + a1.y, a0.z + a1.z, a0.w + a1.w);
    if (lane == 0) g_A[f] = r;
}

// ---------------------------------------------------------------------------
// K2: parallel cross-chunk scan (pair-combined Hillis-Steele over affine
// maps; verified in R7 phase 2). Block = (b, d4-lane g); thread i in [0,256)
// owns chunk pair (2i, 2i+1). Composition (A2,B2)∘(A1,B1)=(A2*A1, A2*B1+B2).
// Garbage in masked chunks only flows toward higher c -> never consumed.
// ---------------------------------------------------------------------------
__global__ void __launch_bounds__(256) k2_scan()
{
    const int b = blockIdx.x;
    const int g = blockIdx.y;     // d4 lane 0..127
    const int i = threadIdx.x;    // pair id 0..255

    const int f0 = b * CC + 2 * i;
    const int f1 = f0 + 1;

    float a0 = g_A[f0];
    float a1 = g_A[f1];
    float4 v0 = ((const float4*)g_Bsum)[(size_t)f0 * D4 + g];
    float4 v1 = ((const float4*)g_Bsum)[(size_t)f1 * D4 + g];

    // combined pair map (apply chunk 2i then 2i+1)
    float  ac = a1 * a0;
    float4 bc = make_float4(fmaf(a1, v0.x, v1.x), fmaf(a1, v0.y, v1.y),
                            fmaf(a1, v0.z, v1.z), fmaf(a1, v0.w, v1.w));

    __shared__ float sA[256];
    __shared__ float4 sB[256];
    sA[i] = ac; sB[i] = bc;
    __syncthreads();
#pragma unroll
    for (int s = 1; s < 256; s <<= 1) {
        float pa = 1.0f;
        float4 pb = make_float4(0.f, 0.f, 0.f, 0.f);
        if (i >= s) { pa = sA[i - s]; pb = sB[i - s]; }
        __syncthreads();
        if (i >= s) {
            bc.x = fmaf(ac, pb.x, bc.x);
            bc.y = fmaf(ac, pb.y, bc.y);
            bc.z = fmaf(ac, pb.z, bc.z);
            bc.w = fmaf(ac, pb.w, bc.w);
            ac *= pa;
            sA[i] = ac; sB[i] = bc;
        }
        __syncthreads();
    }
    // exclusive prefix entering pair i
    float4 Eb = (i == 0) ? make_float4(0.f, 0.f, 0.f, 0.f) : sB[i - 1];
    float4* __restrict__ zi = (float4*)g_Zinit;
    zi[(size_t)f0 * D4 + g] = Eb;
    zi[(size_t)f1 * D4 + g] =
        make_float4(fmaf(a0, Eb.x, v0.x), fmaf(a0, Eb.y, v0.y),
                    fmaf(a0, Eb.z, v0.z), fmaf(a0, Eb.w, v0.w));
}

// ---------------------------------------------------------------------------
// K3: per-chunk local scan seeded with Zinit; mask; streaming-write out.
// Masked chunks zero-fill (streaming stores, no loads). LL=8 loads in one
// front batch; chain is 8 FMAs with x/y/z/w independent.
// ---------------------------------------------------------------------------
__global__ void __launch_bounds__(128) k3_scan_out(
    const float* __restrict__ z, const float* __restrict__ P,
    const int* __restrict__ lengths, float* __restrict__ out)
{
    const int b = blockIdx.x;
    const int c = blockIdx.y;
    const int lane = threadIdx.x;
    const int len = lengths[b];
    const int t0 = c * LL;

    float4* __restrict__ op = (float4*)(out + ((size_t)b * TT + t0) * DD);

    if (t0 >= len) {                 // fully masked: streaming zero-fill
        float4 zero = make_float4(0.f, 0.f, 0.f, 0.f);
#pragma unroll
        for (int k = 0; k < LL; ++k) __stwt(&op[(size_t)k * D4 + lane], zero);
        return;
    }

    // carry load issued early (latency hidden behind P loads)
    float4 zv = ((const float4*)g_Zinit)[(size_t)(b * CC + c) * D4 + lane];

    float pcl[LL];
#pragma unroll
    for (int k = 0; k < LL; ++k) {
        float p = __ldg(&P[b * TT + t0 + k]);
        pcl[k] = fminf(fmaxf(p, 0.0f), 1.0f - 1e-6f);
    }

    const float4* __restrict__ zp =
        (const float4*)(z + ((size_t)b * TT + t0) * DD);

    float4 x0 = zp[0 * D4 + lane];
    float4 x1 = zp[1 * D4 + lane];
    float4 x2 = zp[2 * D4 + lane];
    float4 x3 = zp[3 * D4 + lane];
    float4 x4 = zp[4 * D4 + lane];
    float4 x5 = zp[5 * D4 + lane];
    float4 x6 = zp[6 * D4 + lane];
    float4 x7 = zp[7 * D4 + lane];
    asm volatile("" ::: "memory");   // keep all 8 loads front-batched

#pragma unroll
    for (int k = 0; k < LL; ++k) {
        float4 x = (k == 0) ? x0 : (k == 1) ? x1 : (k == 2) ? x2 : (k == 3) ? x3
                 : (k == 4) ? x4 : (k == 5) ? x5 : (k == 6) ? x6 : x7;
        float q = 1.0f - pcl[k];
        float pe = fmaxf(pcl[k], 1e-6f);
        zv.x = fmaf(q, zv.x, pe * x.x);
        zv.y = fmaf(q, zv.y, pe * x.y);
        zv.z = fmaf(q, zv.z, pe * x.z);
        zv.w = fmaf(q, zv.w, pe * x.w);
        float m = (t0 + k < len) ? 1.0f : 0.0f;
        __stwt(&op[(size_t)k * D4 + lane],
               make_float4(zv.x * m, zv.y * m, zv.z * m, zv.w * m));
    }
}

extern "C" void kernel_launch(void* const* d_in, const int* in_sizes, int n_in,
                              void* d_out, int out_size)
{
    const float* z = (const float*)d_in[0];
    const float* P = (const float*)d_in[1];
    const int* lengths = (const int*)d_in[2];
    float* out = (float*)d_out;

    dim3 gridA(BB, CC);        // b fastest -> masked/active mixed across SMs
    k1_chunk_summary<<<gridA, 128>>>(z, P, lengths);
    dim3 gridS(BB, D4);
    k2_scan<<<gridS, 256>>>();
    k3_scan_out<<<gridA, 128>>>(z, P, lengths, out);
}

// round 11
// speedup vs baseline: 1.4010x; 1.0017x over previous
#include <cuda_runtime.h>

// z_hat [B,T,D] f32, P [B,T] f32, lengths [B] i32 -> out [B,T,D] f32
#define BB 4
#define TT 4096
#define DD 512
#define CC 512              // chunks along T
#define LL 8                // chunk length
#define D4 128              // float4 lanes per row (DD/4)
#define NCHUNK (BB*CC)      // 2048 chunks, f = b*CC + c

// Scratch (__device__ globals; allocation-free rule). idx f = b*CC + c.
__device__ float g_Bsum[NCHUNK * DD];
__device__ float g_A[NCHUNK];
__device__ float g_Zinit[NCHUNK * DD];

// ---------------------------------------------------------------------------
// K1: per-chunk weighted reduction.
// CRITICAL ORDER: the 8 z float4 loads issue FIRST (they do not depend on
// the weights); P loads + weight chain overlap with z loads in flight.
// One DRAM-latency epoch per block instead of two.
// ---------------------------------------------------------------------------
__global__ void __launch_bounds__(128) k1_chunk_summary(
    const float* __restrict__ z, const float* __restrict__ P,
    const int* __restrict__ lengths)
{
    const int b = blockIdx.x;     // fastest -> masked/active mixed across SMs
    const int c = blockIdx.y;
    const int lane = threadIdx.x; // float4 lane over D
    const int len = lengths[b];
    const int t0 = c * LL;
    if (t0 >= len) return;        // masked chunk: state never consumed

    const float4* __restrict__ zp =
        (const float4*)(z + ((size_t)b * TT + t0) * DD);

    // ---- z loads first: 8 independent LDG.128 in flight immediately ----
    float4 x0 = zp[0 * D4 + lane];
    float4 x1 = zp[1 * D4 + lane];
    float4 x2 = zp[2 * D4 + lane];
    float4 x3 = zp[3 * D4 + lane];
    float4 x4 = zp[4 * D4 + lane];
    float4 x5 = zp[5 * D4 + lane];
    float4 x6 = zp[6 * D4 + lane];
    float4 x7 = zp[7 * D4 + lane];

    // ---- P loads + weight chain overlap with the z loads ----
    float pcl[LL];
#pragma unroll
    for (int k = 0; k < LL; ++k) {
        float p = __ldg(&P[b * TT + t0 + k]);     // warp-uniform broadcast
        pcl[k] = fminf(fmaxf(p, 0.0f), 1.0f - 1e-6f);
    }
    float w[LL];
    float r = 1.0f;
#pragma unroll
    for (int k = LL - 1; k >= 0; --k) {
        w[k] = fmaxf(pcl[k], 1e-6f) * r;          // w[k]=pe[k]*prod_{m>k}q[m]
        r *= (1.0f - pcl[k]);
    }

    float4 a0, a1;
    a0.x = w[0] * x0.x; a0.y = w[0] * x0.y; a0.z = w[0] * x0.z; a0.w = w[0] * x0.w;
    a1.x = w[1] * x1.x; a1.y = w[1] * x1.y; a1.z = w[1] * x1.z; a1.w = w[1] * x1.w;
    a0.x = fmaf(w[2], x2.x, a0.x); a0.y = fmaf(w[2], x2.y, a0.y);
    a0.z = fmaf(w[2], x2.z, a0.z); a0.w = fmaf(w[2], x2.w, a0.w);
    a1.x = fmaf(w[3], x3.x, a1.x); a1.y = fmaf(w[3], x3.y, a1.y);
    a1.z = fmaf(w[3], x3.z, a1.z); a1.w = fmaf(w[3], x3.w, a1.w);
    a0.x = fmaf(w[4], x4.x, a0.x); a0.y = fmaf(w[4], x4.y, a0.y);
    a0.z = fmaf(w[4], x4.z, a0.z); a0.w = fmaf(w[4], x4.w, a0.w);
    a1.x = fmaf(w[5], x5.x, a1.x); a1.y = fmaf(w[5], x5.y, a1.y);
    a1.z = fmaf(w[5], x5.z, a1.z); a1.w = fmaf(w[5], x5.w, a1.w);
    a0.x = fmaf(w[6], x6.x, a0.x); a0.y = fmaf(w[6], x6.y, a0.y);
    a0.z = fmaf(w[6], x6.z, a0.z); a0.w = fmaf(w[6], x6.w, a0.w);
    a1.x = fmaf(w[7], x7.x, a1.x); a1.y = fmaf(w[7], x7.y, a1.y);
    a1.z = fmaf(w[7], x7.z, a1.z); a1.w = fmaf(w[7], x7.w, a1.w);

    const int f = b * CC + c;
    ((float4*)g_Bsum)[(size_t)f * D4 + lane] =
        make_float4(a0.x + a1.x, a0.y + a1.y, a0.z + a1.z, a0.w + a1.w);
    if (lane == 0) g_A[f] = r;
}

// ---------------------------------------------------------------------------
// K2: parallel cross-chunk scan (pair-combined Hillis-Steele over affine
// maps). Block = (b, d4-lane g); thread i owns chunk pair (2i, 2i+1).
// Composition (A2,B2)∘(A1,B1)=(A2*A1, A2*B1+B2). Garbage in masked chunks
// only flows toward higher c -> never consumed.
// ---------------------------------------------------------------------------
__global__ void __launch_bounds__(256) k2_scan()
{
    const int b = blockIdx.x;
    const int g = blockIdx.y;     // d4 lane 0..127
    const int i = threadIdx.x;    // pair id 0..255

    const int f0 = b * CC + 2 * i;
    const int f1 = f0 + 1;

    float a0 = g_A[f0];
    float a1 = g_A[f1];
    float4 v0 = ((const float4*)g_Bsum)[(size_t)f0 * D4 + g];
    float4 v1 = ((const float4*)g_Bsum)[(size_t)f1 * D4 + g];

    float  ac = a1 * a0;
    float4 bc = make_float4(fmaf(a1, v0.x, v1.x), fmaf(a1, v0.y, v1.y),
                            fmaf(a1, v0.z, v1.z), fmaf(a1, v0.w, v1.w));

    __shared__ float sA[256];
    __shared__ float4 sB[256];
    sA[i] = ac; sB[i] = bc;
    __syncthreads();
#pragma unroll
    for (int s = 1; s < 256; s <<= 1) {
        float pa = 1.0f;
        float4 pb = make_float4(0.f, 0.f, 0.f, 0.f);
        if (i >= s) { pa = sA[i - s]; pb = sB[i - s]; }
        __syncthreads();
        if (i >= s) {
            bc.x = fmaf(ac, pb.x, bc.x);
            bc.y = fmaf(ac, pb.y, bc.y);
            bc.z = fmaf(ac, pb.z, bc.z);
            bc.w = fmaf(ac, pb.w, bc.w);
            ac *= pa;
            sA[i] = ac; sB[i] = bc;
        }
        __syncthreads();
    }
    float4 Eb = (i == 0) ? make_float4(0.f, 0.f, 0.f, 0.f) : sB[i - 1];
    float4* __restrict__ zi = (float4*)g_Zinit;
    zi[(size_t)f0 * D4 + g] = Eb;
    zi[(size_t)f1 * D4 + g] =
        make_float4(fmaf(a0, Eb.x, v0.x), fmaf(a0, Eb.y, v0.y),
                    fmaf(a0, Eb.z, v0.z), fmaf(a0, Eb.w, v0.w));
}

// ---------------------------------------------------------------------------
// K3: per-chunk local scan seeded with Zinit; streaming stores.
// Same load-first ordering: z loads + Zinit load issue before P/weights.
// Masked chunks zero-fill with no loads.
// ---------------------------------------------------------------------------
__global__ void __launch_bounds__(128) k3_scan_out(
    const float* __restrict__ z, const float* __restrict__ P,
    const int* __restrict__ lengths, float* __restrict__ out)
{
    const int b = blockIdx.x;
    const int c = blockIdx.y;
    const int lane = threadIdx.x;
    const int len = lengths[b];
    const int t0 = c * LL;

    float4* __restrict__ op = (float4*)(out + ((size_t)b * TT + t0) * DD);

    if (t0 >= len) {                 // fully masked: streaming zero-fill
        float4 zero = make_float4(0.f, 0.f, 0.f, 0.f);
#pragma unroll
        for (int k = 0; k < LL; ++k) __stwt(&op[(size_t)k * D4 + lane], zero);
        return;
    }

    const float4* __restrict__ zp =
        (const float4*)(z + ((size_t)b * TT + t0) * DD);

    // ---- all loads first: 8 z rows + carry, then P (all independent) ----
    float4 x0 = zp[0 * D4 + lane];
    float4 x1 = zp[1 * D4 + lane];
    float4 x2 = zp[2 * D4 + lane];
    float4 x3 = zp[3 * D4 + lane];
    float4 x4 = zp[4 * D4 + lane];
    float4 x5 = zp[5 * D4 + lane];
    float4 x6 = zp[6 * D4 + lane];
    float4 x7 = zp[7 * D4 + lane];
    float4 zv = ((const float4*)g_Zinit)[(size_t)(b * CC + c) * D4 + lane];

    float pcl[LL];
#pragma unroll
    for (int k = 0; k < LL; ++k) {
        float p = __ldg(&P[b * TT + t0 + k]);
        pcl[k] = fminf(fmaxf(p, 0.0f), 1.0f - 1e-6f);
    }

#pragma unroll
    for (int k = 0; k < LL; ++k) {
        float4 x = (k == 0) ? x0 : (k == 1) ? x1 : (k == 2) ? x2 : (k == 3) ? x3
                 : (k == 4) ? x4 : (k == 5) ? x5 : (k == 6) ? x6 : x7;
        float q = 1.0f - pcl[k];
        float pe = fmaxf(pcl[k], 1e-6f);
        zv.x = fmaf(q, zv.x, pe * x.x);
        zv.y = fmaf(q, zv.y, pe * x.y);
        zv.z = fmaf(q, zv.z, pe * x.z);
        zv.w = fmaf(q, zv.w, pe * x.w);
        float m = (t0 + k < len) ? 1.0f : 0.0f;
        __stwt(&op[(size_t)k * D4 + lane],
               make_float4(zv.x * m, zv.y * m, zv.z * m, zv.w * m));
    }
}

extern "C" void kernel_launch(void* const* d_in, const int* in_sizes, int n_in,
                              void* d_out, int out_size)
{
    const float* z = (const float*)d_in[0];
    const float* P = (const float*)d_in[1];
    const int* lengths = (const int*)d_in[2];
    float* out = (float*)d_out;

    dim3 gridA(BB, CC);        // b fastest -> masked/active mixed across SMs
    k1_chunk_summary<<<gridA, 128>>>(z, P, lengths);
    dim3 gridS(BB, D4);
    k2_scan<<<gridS, 256>>>();
    k3_scan_out<<<gridA, 128>>>(z, P, lengths, out);
}